// round 9
// baseline (speedup 1.0000x reference)
#include <cuda_runtime.h>
#include <cstdint>
#include <math.h>

// Problem constants (fixed shapes from reference)
#define NK 1024            // num embeddings
#define ND 256             // embedding dim
#define HW 1024            // H*W = 32*32
#define NB 32              // batch
#define NN 32768           // N = NB*HW
#define OUT_ELEMS 8388608  // NB*ND*HW

// ---------------- device scratch (no allocations allowed) ----------------
__device__ alignas(16) float g_Et[ND * NK];     // transposed codebook [d][k]
__device__ alignas(16) float g_enorm[NK];       // ||e_k||^2
__device__ int   g_counts[NK];
__device__ int   g_indices[NN];
__device__ float g_partials[256];               // per-block SSE partials (deterministic)

// ---------------- f32x2 packed-FMA helpers (sm_103a) ----------------
// Each 32-bit lane behaves exactly like scalar fma.rn.f32 -> a packed lane is a
// bit-exact sequential fused-FMA chain (matches the reference GEMM accumulation).
__device__ __forceinline__ unsigned long long pack2(float x) {
    unsigned long long r;
    asm("mov.b64 %0, {%1, %1};" : "=l"(r) : "f"(x));
    return r;
}
__device__ __forceinline__ void ffma2(unsigned long long& d,
                                      unsigned long long a,
                                      unsigned long long b) {
    asm("fma.rn.f32x2 %0, %1, %2, %0;" : "+l"(d) : "l"(a), "l"(b));
}
__device__ __forceinline__ void unpack2(unsigned long long v, float& lo, float& hi) {
    asm("mov.b64 {%0, %1}, %2;" : "=f"(lo), "=f"(hi) : "l"(v));
}

// ---------------- cp.async helpers ----------------
__device__ __forceinline__ void cpa16(float* sptr, const float* gptr) {
    uint32_t sa = (uint32_t)__cvta_generic_to_shared(sptr);
    asm volatile("cp.async.cg.shared.global [%0], [%1], 16;" :: "r"(sa), "l"(gptr));
}
__device__ __forceinline__ void cpa_commit() {
    asm volatile("cp.async.commit_group;");
}
__device__ __forceinline__ void cpa_wait0() {
    asm volatile("cp.async.wait_group 0;");
}

// ================= kernel 0: transpose E, code norms, zero counts =================
__global__ __launch_bounds__(256)
void prep_kernel(const float* __restrict__ E) {
    const int k = blockIdx.x;      // 0..1023
    const int d = threadIdx.x;     // 0..255
    float v = E[k * ND + d];
    g_Et[d * NK + k] = v;

    float s = __fmul_rn(v, v);
    #pragma unroll
    for (int o = 16; o > 0; o >>= 1) s += __shfl_xor_sync(0xffffffffu, s, o);
    __shared__ float ws[8];
    if ((threadIdx.x & 31) == 0) ws[threadIdx.x >> 5] = s;
    __syncthreads();
    if (threadIdx.x == 0) {
        float t = 0.f;
        #pragma unroll
        for (int w = 0; w < 8; w++) t += ws[w];
        g_enorm[k] = t;
        g_counts[k] = 0;
    }
}

// ================= kernel 1: fused distance GEMM + argmin (+ fused row norms) ========
// Grid: 256 CTAs x 256 thr. CTA tile: BM=128 rows x BN=128 codes, BK=32, 8x8 microtile.
// Double-buffered cp.async tiles; row norms ||x||^2 accumulated bit-exactly
// (d-ascending fadd/fmul chain) from the staged X tiles during ct==0.
// dist = fl( fl(S + esq) - 2*dot ), dot = sequential fused-FMA chain over d.
//
// Dynamic smem layout (floats):
//   Xs: [2][32][128] at 0       Es: [2][32][128] at 8192
//   srow[128] at 16384          red-overlay (v[128][16], idx[128][16]) at 0
#define ARGMIN_SMEM_FLOATS (2*32*128 + 2*32*128 + 128)

__global__ __launch_bounds__(256, 2)
void argmin_kernel(const float* __restrict__ X) {
    extern __shared__ float dyn[];
    float* Xs   = dyn;                 // [2][32][128]
    float* Es   = dyn + 8192;          // [2][32][128]
    float* srow = dyn + 16384;         // [128]
    float* redv = dyn;                 // [128][16] overlay (used at the end)
    int*   redi = (int*)(dyn + 2048);  // [128][16] overlay

    const int tid = threadIdx.x;
    const int tx = tid & 15;            // column group (8 codes)
    const int ty = tid >> 4;            // row group (8 rows)
    const int row0 = blockIdx.x * 128;
    const int b   = row0 >> 10;
    const int hw0 = row0 & 1023;
    const float* Xbase = X + (size_t)b * (ND * HW) + hw0;

    // cooperative load coordinates (same for every chunk)
    const int lc0 = tid >> 5;                 // dim-within-chunk for it slice 0
    const int lr4 = (tid & 31) << 2;          // row*4 within 128

    float Srow[8];
    float bestv[8];
    int   besti[8];
    #pragma unroll
    for (int i = 0; i < 8; i++) { bestv[i] = 3.4e38f; besti[i] = 0; }
    float rs = 0.f;                           // fused row-norm accumulator (tid<128)

    for (int ct = 0; ct < 8; ct++) {          // code tiles of 128
        const int k0 = ct * 128;
        unsigned long long acc[8][4];         // 8 rows x 4 col-pairs (f32x2)
        #pragma unroll
        for (int i = 0; i < 8; i++)
            #pragma unroll
            for (int j = 0; j < 4; j++) acc[i][j] = 0ULL;

        // preload dk=0 into buffer 0
        #pragma unroll
        for (int it = 0; it < 4; it++) {
            const int c = lc0 + it * 8;
            cpa16(&Xs[c * 128 + lr4], Xbase + (size_t)c * HW + lr4);
            cpa16(&Es[c * 128 + lr4], &g_Et[(size_t)c * NK + k0 + lr4]);
        }
        cpa_commit();

        for (int dk = 0; dk < 8; dk++) {      // D chunks of 32, ascending d
            cpa_wait0();
            __syncthreads();

            if (dk < 7) {                     // prefetch next chunk into other buffer
                const int nb = ((dk + 1) & 1) * 4096;
                const int d0n = (dk + 1) * 32;
                #pragma unroll
                for (int it = 0; it < 4; it++) {
                    const int c = lc0 + it * 8;
                    cpa16(&Xs[nb + c * 128 + lr4], Xbase + (size_t)(d0n + c) * HW + lr4);
                    cpa16(&Es[nb + c * 128 + lr4], &g_Et[(size_t)(d0n + c) * NK + k0 + lr4]);
                }
                cpa_commit();
            }

            const float* XsB = Xs + (dk & 1) * 4096;
            const float* EsB = Es + (dk & 1) * 4096;

            // fused ||x||^2: strict d-ascending chain acc = fadd(acc, fmul(x,x))
            if (ct == 0 && tid < 128) {
                #pragma unroll 8
                for (int kk = 0; kk < 32; kk++) {
                    const float v = XsB[kk * 128 + tid];
                    rs = __fadd_rn(rs, __fmul_rn(v, v));
                }
            }

            #pragma unroll 4
            for (int kk = 0; kk < 32; kk++) {    // ascending within chunk
                const float4 xa = *reinterpret_cast<const float4*>(&XsB[kk * 128 + ty * 8]);
                const float4 xb = *reinterpret_cast<const float4*>(&XsB[kk * 128 + ty * 8 + 4]);
                const ulonglong2 ea = *reinterpret_cast<const ulonglong2*>(&EsB[kk * 128 + tx * 8]);
                const ulonglong2 eb = *reinterpret_cast<const ulonglong2*>(&EsB[kk * 128 + tx * 8 + 4]);
                const float xs[8] = {xa.x, xa.y, xa.z, xa.w, xb.x, xb.y, xb.z, xb.w};
                const unsigned long long es[4] = {ea.x, ea.y, eb.x, eb.y};
                #pragma unroll
                for (int i = 0; i < 8; i++) {
                    const unsigned long long xp = pack2(xs[i]);
                    #pragma unroll
                    for (int j = 0; j < 4; j++) ffma2(acc[i][j], xp, es[j]);
                }
            }
        }

        if (ct == 0) {                         // publish row norms once
            if (tid < 128) srow[tid] = rs;
            __syncthreads();
            #pragma unroll
            for (int i = 0; i < 8; i++) Srow[i] = srow[ty * 8 + i];
        }

        // Fold this code tile into the running per-row argmin, on the
        // reference's fp32 lattice: fl( fl(S + esq_k) - 2*dot ).
        const float4 en0 = __ldg(reinterpret_cast<const float4*>(&g_enorm[k0 + tx * 8]));
        const float4 en1 = __ldg(reinterpret_cast<const float4*>(&g_enorm[k0 + tx * 8 + 4]));
        const float en[8] = {en0.x, en0.y, en0.z, en0.w, en1.x, en1.y, en1.z, en1.w};
        #pragma unroll
        for (int i = 0; i < 8; i++) {
            #pragma unroll
            for (int jp = 0; jp < 4; jp++) {
                float dlo, dhi;
                unpack2(acc[i][jp], dlo, dhi);
                const int c0 = k0 + tx * 8 + jp * 2;
                const float t0 = __fadd_rn(Srow[i], en[jp * 2]);
                const float t1 = __fadd_rn(Srow[i], en[jp * 2 + 1]);
                const float dist0 = __fsub_rn(t0, 2.0f * dlo);   // 2x exact
                const float dist1 = __fsub_rn(t1, 2.0f * dhi);
                // ascending column order + strict < keeps the FIRST minimum
                if (dist0 < bestv[i]) { bestv[i] = dist0; besti[i] = c0; }
                if (dist1 < bestv[i]) { bestv[i] = dist1; besti[i] = c0 + 1; }
            }
        }
    }

    // Cross-tx reduction per row; tie-break on index to match jnp.argmin
    // "first minimum" semantics (ties are real due to lattice rounding).
    __syncthreads();
    #pragma unroll
    for (int i = 0; i < 8; i++) {
        redv[(ty * 8 + i) * 16 + tx] = bestv[i];
        redi[(ty * 8 + i) * 16 + tx] = besti[i];
    }
    __syncthreads();
    if (tid < 128) {
        float bv = redv[tid * 16];
        int   bi = redi[tid * 16];
        #pragma unroll
        for (int t = 1; t < 16; t++) {
            const float v = redv[tid * 16 + t];
            const int  ix = redi[tid * 16 + t];
            if (v < bv || (v == bv && ix < bi)) { bv = v; bi = ix; }
        }
        g_indices[row0 + tid] = bi;
        atomicAdd(&g_counts[bi], 1);   // integer atomic: deterministic
    }
}

// ================= kernel 2: gather + straight-through output + SSE =================
// Per 32-d chunk: gather codebook rows COALESCED from row-major E into smem
// (kills the 4KB-stride 32B-sector gather that made R5's epilogue L2-bound),
// then stream X/out coalesced with float4 smem reads.
__global__ __launch_bounds__(256)
void epilogue_kernel(const float* __restrict__ X, const float* __restrict__ E,
                     float* __restrict__ out) {
    __shared__ int idxs[128];
    __shared__ float Qs[32][132];      // [dloc][row], pad 4 -> float4 reads conflict-free
    __shared__ float ws[8];
    const int tid = threadIdx.x;
    const int w = tid >> 5, lane = tid & 31;
    const int row0 = blockIdx.x * 128;
    const int b   = row0 >> 10;
    const int hw0 = row0 & 1023;
    const size_t base = (size_t)b * (ND * HW) + hw0;

    if (tid < 128) idxs[tid] = g_indices[row0 + tid];
    __syncthreads();

    float acc = 0.f;
    for (int ch = 0; ch < 8; ch++) {
        const int d0 = ch * 32;
        // gather phase: warp w loads rows w*16..w*16+15, coalesced along d
        #pragma unroll
        for (int j = 0; j < 16; j++) {
            const int r = w * 16 + j;
            Qs[lane][r] = __ldg(&E[(size_t)idxs[r] * ND + d0 + lane]);
        }
        __syncthreads();
        // stream phase
        #pragma unroll
        for (int it = 0; it < 4; it++) {
            const int slot = it * 256 + tid;       // 0..1023
            const int dloc = slot >> 5;            // 0..31
            const int r4   = (slot & 31) << 2;     // 0..124
            const size_t off = base + (size_t)(d0 + dloc) * HW + r4;
            const float4 x = __ldg(reinterpret_cast<const float4*>(X + off));
            const float4 q = *reinterpret_cast<const float4*>(&Qs[dloc][r4]);
            // reference: diff = fl(q - x); out = fl(x + diff)
            const float dx = __fsub_rn(q.x, x.x);
            const float dy = __fsub_rn(q.y, x.y);
            const float dz = __fsub_rn(q.z, x.z);
            const float dw = __fsub_rn(q.w, x.w);
            acc += dx * dx + dy * dy + dz * dz + dw * dw;
            float4 o;
            o.x = __fadd_rn(x.x, dx); o.y = __fadd_rn(x.y, dy);
            o.z = __fadd_rn(x.z, dz); o.w = __fadd_rn(x.w, dw);
            *reinterpret_cast<float4*>(out + off) = o;
        }
        __syncthreads();
    }
    #pragma unroll
    for (int o = 16; o > 0; o >>= 1) acc += __shfl_xor_sync(0xffffffffu, acc, o);
    if ((tid & 31) == 0) ws[tid >> 5] = acc;
    __syncthreads();
    if (tid == 0) {
        float t = 0.f;
        #pragma unroll
        for (int ww = 0; ww < 8; ww++) t += ws[ww];
        g_partials[blockIdx.x] = t;   // plain store: deterministic reduction
    }
}

// ================= kernel 3: loss + perplexity scalars =================
__global__ __launch_bounds__(256)
void finalize_kernel(float* __restrict__ out, int out_size) {
    __shared__ float ws[8];
    const int tid = threadIdx.x;

    // --- SSE over 256 partials ---
    float s = g_partials[tid];
    #pragma unroll
    for (int o = 16; o > 0; o >>= 1) s += __shfl_xor_sync(0xffffffffu, s, o);
    if ((tid & 31) == 0) ws[tid >> 5] = s;
    __syncthreads();
    float sse = 0.f;
    if (tid == 0) {
        #pragma unroll
        for (int w = 0; w < 8; w++) sse += ws[w];
    }
    __syncthreads();

    // --- entropy over counts (counts/N is exact: /2^15) ---
    float ent = 0.f;
    #pragma unroll
    for (int k = tid; k < NK; k += 256) {
        const float p = (float)g_counts[k] * (1.0f / (float)NN);
        ent += p * logf(p + 1e-10f);
    }
    #pragma unroll
    for (int o = 16; o > 0; o >>= 1) ent += __shfl_xor_sync(0xffffffffu, ent, o);
    if ((tid & 31) == 0) ws[tid >> 5] = ent;
    __syncthreads();
    if (tid == 0) {
        float e = 0.f;
        #pragma unroll
        for (int w = 0; w < 8; w++) e += ws[w];
        if (out_size >= OUT_ELEMS + 2) {
            // loss = q_latent + 0.25*e_latent; both equal mean((q-x)^2) in value
            out[OUT_ELEMS]     = 1.25f * sse / (float)OUT_ELEMS;
            out[OUT_ELEMS + 1] = expf(-e);
        }
    }
}

// ================= launcher =================
extern "C" void kernel_launch(void* const* d_in, const int* in_sizes, int n_in,
                              void* d_out, int out_size) {
    const float* X = (const float*)d_in[0];   // inputs [32,256,32,32]
    const float* E = (const float*)d_in[1];   // embedding_weight [1024,256]
    float* out = (float*)d_out;

    static bool attr_done = false;
    if (!attr_done) {
        cudaFuncSetAttribute(argmin_kernel,
                             cudaFuncAttributeMaxDynamicSharedMemorySize,
                             ARGMIN_SMEM_FLOATS * (int)sizeof(float));
        attr_done = true;
    }

    prep_kernel<<<NK, 256>>>(E);
    argmin_kernel<<<NN / 128, 256, ARGMIN_SMEM_FLOATS * sizeof(float)>>>(X);
    epilogue_kernel<<<NN / 128, 256>>>(X, E, out);
    finalize_kernel<<<1, 256>>>(out, out_size);
}